// round 8
// baseline (speedup 1.0000x reference)
#include <cuda_runtime.h>
#include <cuda_bf16.h>
#include <math_constants.h>
#include <cstdint>

#define BB   4
#define NN   8192
#define SS   2048
#define D1   128
#define D2   256
#define CIN  384
#define CMID 256
#define COUT 256
#define NT   (NN / 128)   // 64 n-tiles

// ---------------- scratch (device globals; referenced ONLY from device code) ----------------
__device__ __align__(16) __nv_bfloat16 g_B1hi[(size_t)BB * NN * CIN];
__device__ __align__(16) __nv_bfloat16 g_B1lo[(size_t)BB * NN * CIN];
__device__ __align__(16) __nv_bfloat16 g_B2hi[(size_t)BB * NN * CMID];
__device__ __align__(16) __nv_bfloat16 g_B2lo[(size_t)BB * NN * CMID];
__device__ __align__(16) __nv_bfloat16 g_W1hi[CMID * CIN], g_W1lo[CMID * CIN];
__device__ __align__(16) __nv_bfloat16 g_W2hi[COUT * CMID], g_W2lo[COUT * CMID];
__device__ float g_Y[(size_t)BB * NN * CMID];   // GEMM1 out fp32 [b][n][c]
__device__ float g_O[(size_t)BB * NN * COUT];   // GEMM2 out fp32 [b][n][c]
__device__ float g_F2T[(size_t)BB * SS * D2];   // feature2 transposed [b][s][c]
__device__ float g_w[BB * NN * 3];
__device__ int   g_idx[BB * NN * 3];
__device__ float g_scale[CMID];
__device__ float g_shift[CMID];
__device__ float g_psum[256 * 256];             // slot = b*NT + n-tile
__device__ float g_psq[256 * 256];

// ---------------- helpers ----------------
__device__ __forceinline__ uint32_t smem_u32(const void* p) {
    uint32_t a;
    asm("{ .reg .u64 t; cvta.to.shared.u64 t, %1; cvt.u32.u64 %0, t; }" : "=r"(a) : "l"(p));
    return a;
}
__device__ __forceinline__ void cp16(uint32_t dst, const void* src) {
    asm volatile("cp.async.ca.shared.global [%0], [%1], 16;" :: "r"(dst), "l"(src));
}
__device__ __forceinline__ void cp_commit_wait() {
    asm volatile("cp.async.commit_group;" ::: "memory");
    asm volatile("cp.async.wait_group 0;" ::: "memory");
}
__device__ __forceinline__ void ldm_x4(uint32_t addr, uint32_t* f) {
    asm volatile("ldmatrix.sync.aligned.m8n8.x4.shared.b16 {%0,%1,%2,%3}, [%4];"
                 : "=r"(f[0]), "=r"(f[1]), "=r"(f[2]), "=r"(f[3]) : "r"(addr));
}
__device__ __forceinline__ void mma16816(float* c, const uint32_t* a, const uint32_t* b) {
    asm volatile("mma.sync.aligned.m16n8k16.row.col.f32.bf16.bf16.f32 "
                 "{%0,%1,%2,%3},{%4,%5,%6,%7},{%8,%9},{%0,%1,%2,%3};"
                 : "+f"(c[0]), "+f"(c[1]), "+f"(c[2]), "+f"(c[3])
                 : "r"(a[0]), "r"(a[1]), "r"(a[2]), "r"(a[3]), "r"(b[0]), "r"(b[1]));
}
__device__ __forceinline__ void split_bf16(float v, __nv_bfloat16& h, __nv_bfloat16& l) {
    h = __float2bfloat16_rn(v);
    l = __float2bfloat16_rn(v - __bfloat162float(h));
}

// ---------------- 3-NN ----------------
__device__ __forceinline__ void top3_insert(float d, int i,
                                            float& d0, float& d1, float& d2v,
                                            int& i0, int& i1, int& i2) {
    bool b2 = (d < d2v) || (d == d2v && i < i2);
    if (!b2) return;
    bool b1 = (d < d1) || (d == d1 && i < i1);
    bool b0 = (d < d0) || (d == d0 && i < i0);
    if (b0)      { d2v = d1; i2 = i1; d1 = d0; i1 = i0; d0 = d;  i0 = i; }
    else if (b1) { d2v = d1; i2 = i1; d1 = d;  i1 = i; }
    else         { d2v = d;  i2 = i; }
}

__global__ void __launch_bounds__(256) knn_kernel(const float* __restrict__ pos1,
                                                  const float* __restrict__ pos2) {
    __shared__ float4 sp[SS];
    int b = blockIdx.y;
    const float* p2 = pos2 + (size_t)b * 3 * SS;
    for (int s = threadIdx.x; s < SS; s += 256) {
        float x = p2[s], y = p2[SS + s], z = p2[2 * SS + s];
        sp[s] = make_float4(x, y, z, x * x + y * y + z * z);
    }
    __syncthreads();
    int wid = threadIdx.x >> 5, lane = threadIdx.x & 31;
    int n = blockIdx.x * 8 + wid;
    const float* p1 = pos1 + (size_t)b * 3 * NN;
    float x1 = p1[n], y1 = p1[NN + n], z1 = p1[2 * NN + n];
    float n1 = x1 * x1 + y1 * y1 + z1 * z1;
    float nx = -2.0f * x1, ny = -2.0f * y1, nz = -2.0f * z1;
    float d0 = CUDART_INF_F, d1 = CUDART_INF_F, d2v = CUDART_INF_F;
    int i0 = 0x7fffffff, i1 = 0x7fffffff, i2 = 0x7fffffff;
    for (int s = lane; s < SS; s += 32) {
        float4 p = sp[s];
        float d = fmaf(nx, p.x, fmaf(ny, p.y, fmaf(nz, p.z, p.w + n1)));
        top3_insert(d, s, d0, d1, d2v, i0, i1, i2);
    }
    for (int off = 16; off; off >>= 1) {
        float od0 = __shfl_down_sync(0xffffffffu, d0, off);
        float od1 = __shfl_down_sync(0xffffffffu, d1, off);
        float od2 = __shfl_down_sync(0xffffffffu, d2v, off);
        int   oi0 = __shfl_down_sync(0xffffffffu, i0, off);
        int   oi1 = __shfl_down_sync(0xffffffffu, i1, off);
        int   oi2 = __shfl_down_sync(0xffffffffu, i2, off);
        top3_insert(od0, oi0, d0, d1, d2v, i0, i1, i2);
        top3_insert(od1, oi1, d0, d1, d2v, i0, i1, i2);
        top3_insert(od2, oi2, d0, d1, d2v, i0, i1, i2);
    }
    if (lane == 0) {
        float w0 = 1.0f / fmaxf(d0, 1e-10f);
        float w1 = 1.0f / fmaxf(d1, 1e-10f);
        float w2 = 1.0f / fmaxf(d2v, 1e-10f);
        float ws = w0 + w1 + w2;
        int base = (b * NN + n) * 3;
        g_w[base + 0] = w0 / ws;  g_idx[base + 0] = i0;
        g_w[base + 1] = w1 / ws;  g_idx[base + 1] = i1;
        g_w[base + 2] = w2 / ws;  g_idx[base + 2] = i2;
    }
}

// ---------------- transpose feature2 -> g_F2T [b][s][c] ----------------
__global__ void __launch_bounds__(256) tr_f2_kernel(const float* __restrict__ f2) {
    __shared__ float t[32][33];
    int b = blockIdx.z, c0 = blockIdx.y * 32, s0 = blockIdx.x * 32;
    int tx = threadIdx.x & 31, ty = threadIdx.x >> 5;
#pragma unroll
    for (int r = 0; r < 4; r++) {
        int i = ty + r * 8;
        t[i][tx] = f2[((size_t)b * D2 + c0 + i) * SS + s0 + tx];
    }
    __syncthreads();
#pragma unroll
    for (int r = 0; r < 4; r++) {
        int i = ty + r * 8;
        g_F2T[((size_t)b * SS + s0 + i) * 256 + c0 + tx] = t[tx][i];
    }
}

// ---------------- transpose feature1 -> bf16 hi/lo cols [256,384) ----------------
__global__ void __launch_bounds__(256) tr_f1_kernel(const float* __restrict__ f1) {
    __shared__ float t[32][33];
    int b = blockIdx.z, c0 = blockIdx.y * 32, n0 = blockIdx.x * 32;
    int tx = threadIdx.x & 31, ty = threadIdx.x >> 5;
#pragma unroll
    for (int r = 0; r < 4; r++) {
        int i = ty + r * 8;
        t[i][tx] = f1[((size_t)b * D1 + c0 + i) * NN + n0 + tx];
    }
    __syncthreads();
#pragma unroll
    for (int r = 0; r < 4; r++) {
        int i = ty + r * 8;
        __nv_bfloat16 h, l;
        split_bf16(t[tx][i], h, l);
        size_t idx = ((size_t)b * NN + n0 + i) * CIN + 256 + c0 + tx;
        g_B1hi[idx] = h;
        g_B1lo[idx] = l;
    }
}

// ---------------- interp: thread = channel, block = 32 points; emits bf16 hi/lo ----------------
__global__ void __launch_bounds__(256) interp_kernel() {
    __shared__ int   sj[32 * 3];
    __shared__ float sw_[32 * 3];
    int b = blockIdx.y, n0 = blockIdx.x * 32;
    int tid = threadIdx.x;
    if (tid < 96) {
        int base = (b * NN + n0) * 3;
        sj[tid]  = g_idx[base + tid];
        sw_[tid] = g_w[base + tid];
    }
    __syncthreads();
    const float* f2t = g_F2T + (size_t)b * SS * 256;
#pragma unroll 4
    for (int p = 0; p < 32; p++) {
        int   j0 = sj[p * 3], j1 = sj[p * 3 + 1], j2 = sj[p * 3 + 2];
        float w0 = sw_[p * 3], w1 = sw_[p * 3 + 1], w2 = sw_[p * 3 + 2];
        float v = fmaf(w2, f2t[(size_t)j2 * 256 + tid],
                  fmaf(w1, f2t[(size_t)j1 * 256 + tid],
                       w0 * f2t[(size_t)j0 * 256 + tid]));
        __nv_bfloat16 h, l;
        split_bf16(v, h, l);
        size_t idx = ((size_t)b * NN + n0 + p) * CIN + tid;
        g_B1hi[idx] = h;
        g_B1lo[idx] = l;
    }
}

// ---------------- weight split (WHICH selects target globals in device code) ----------------
template <int WHICH>
__global__ void __launch_bounds__(256) wsplit_kernel(const float* __restrict__ W, int total) {
    int i = blockIdx.x * 256 + threadIdx.x;
    if (i < total) {
        __nv_bfloat16 h, l;
        split_bf16(W[i], h, l);
        if (WHICH == 0) { g_W1hi[i] = h; g_W1lo[i] = l; }
        else            { g_W2hi[i] = h; g_W2lo[i] = l; }
    }
}

// ---------------- prep2: y -> relu(bn1(y)) -> bf16 hi/lo ----------------
__global__ void __launch_bounds__(256) prep2_kernel() {
    int i = blockIdx.x * 256 + threadIdx.x;   // float4 index over BB*NN*256/4
    int c0 = (i & 63) * 4;                    // 4 consecutive channels
    float4 v = ((const float4*)g_Y)[i];
    float r0 = fmaxf(fmaf(v.x, g_scale[c0 + 0], g_shift[c0 + 0]), 0.0f);
    float r1 = fmaxf(fmaf(v.y, g_scale[c0 + 1], g_shift[c0 + 1]), 0.0f);
    float r2 = fmaxf(fmaf(v.z, g_scale[c0 + 2], g_shift[c0 + 2]), 0.0f);
    float r3 = fmaxf(fmaf(v.w, g_scale[c0 + 3], g_shift[c0 + 3]), 0.0f);
    __nv_bfloat16 h0, l0, h1, l1, h2, l2, h3, l3;
    split_bf16(r0, h0, l0); split_bf16(r1, h1, l1);
    split_bf16(r2, h2, l2); split_bf16(r3, h3, l3);
    __nv_bfloat162 ph0 = __halves2bfloat162(h0, h1), ph1 = __halves2bfloat162(h2, h3);
    __nv_bfloat162 pl0 = __halves2bfloat162(l0, l1), pl1 = __halves2bfloat162(l2, l3);
    ((uint2*)g_B2hi)[i] = make_uint2(*(uint32_t*)&ph0, *(uint32_t*)&ph1);
    ((uint2*)g_B2lo)[i] = make_uint2(*(uint32_t*)&pl0, *(uint32_t*)&pl1);
}

// ---------------- bf16-split HMMA GEMM (pure cp.async mainloop) ----------------
// out[n][m] = sum_k B[n][k] * W[m][k] + bias[m], stored [n][c] stride 256.
// MODE 0: W1/B1 -> g_Y (K=CIN).  MODE 1: W2/B2 -> g_O (K=CMID).
#define RS 40

template <int K, int MODE>
__global__ void __launch_bounds__(256) gemm_tc(const float* __restrict__ bias) {
    __shared__ __align__(16) uint16_t sAhi[128 * RS];
    __shared__ __align__(16) uint16_t sAlo[128 * RS];
    __shared__ __align__(16) uint16_t sBhi[128 * RS];
    __shared__ __align__(16) uint16_t sBlo[128 * RS];

    int tid = threadIdx.x, wid = tid >> 5, lane = tid & 31;
    int b = blockIdx.z, m0 = blockIdx.y * 128, n0 = blockIdx.x * 128;
    int wm = wid >> 2, wn = wid & 3;     // warp tile: (wm*64, wn*32)

    const __nv_bfloat16* Ahi  = (MODE == 0) ? g_W1hi : g_W2hi;
    const __nv_bfloat16* Alo  = (MODE == 0) ? g_W1lo : g_W2lo;
    const __nv_bfloat16* BhiB = ((MODE == 0) ? g_B1hi : g_B2hi) + (size_t)b * NN * K;
    const __nv_bfloat16* BloB = ((MODE == 0) ? g_B1lo : g_B2lo) + (size_t)b * NN * K;
    float* outp               = (MODE == 0) ? g_Y : g_O;

    const int r  = tid >> 1;          // tile row 0..127
    const int kq = (tid & 1) * 16;    // k sub-offset (elements)

    uint32_t uAhi = smem_u32(sAhi), uAlo = smem_u32(sAlo);
    uint32_t uBhi = smem_u32(sBhi), uBlo = smem_u32(sBlo);

    uint32_t dsta = (uint32_t)(r * RS + kq) * 2;
    size_t   srcaA = (size_t)(m0 + r) * K + kq;
    size_t   srcaB = (size_t)(n0 + r) * K + kq;

    // ldmatrix per-lane addresses (element offsets)
    int arow = wm * 64 + (lane & 15);                     // + mi*16
    int acol = (lane >> 4) * 8;                           // + kk*16
    int brow = wn * 32 + (lane & 7) + ((lane >> 4) << 3); // + nb*16
    int bcol = ((lane >> 3) & 1) * 8;                     // + kk*16
    uint32_t aoff = (uint32_t)(arow * RS + acol) * 2;
    uint32_t boff = (uint32_t)(brow * RS + bcol) * 2;

    float acc[4][4][4];
#pragma unroll
    for (int i = 0; i < 4; i++)
#pragma unroll
        for (int j = 0; j < 4; j++)
#pragma unroll
            for (int q = 0; q < 4; q++) acc[i][j][q] = 0.0f;

    const int NCH = K / 32;
    for (int c = 0; c < NCH; c++) {
        size_t ka = srcaA + c * 32;
        size_t kb = srcaB + c * 32;
        cp16(uAhi + dsta,      Ahi + ka);
        cp16(uAhi + dsta + 16, Ahi + ka + 8);
        cp16(uAlo + dsta,      Alo + ka);
        cp16(uAlo + dsta + 16, Alo + ka + 8);
        cp16(uBhi + dsta,      BhiB + kb);
        cp16(uBhi + dsta + 16, BhiB + kb + 8);
        cp16(uBlo + dsta,      BloB + kb);
        cp16(uBlo + dsta + 16, BloB + kb + 8);
        cp_commit_wait();
        __syncthreads();

#pragma unroll
        for (int kk = 0; kk < 2; kk++) {
            uint32_t kadd = (uint32_t)(kk * 16) * 2;
            uint32_t ah[4][4], bf[4][2], tmp[4];
            // A hi frags
#pragma unroll
            for (int mi = 0; mi < 4; mi++)
                ldm_x4(uAhi + aoff + kadd + (uint32_t)(mi * 16 * RS) * 2, ah[mi]);
            // B hi frags
            ldm_x4(uBhi + boff + kadd, tmp);
            bf[0][0] = tmp[0]; bf[0][1] = tmp[1]; bf[1][0] = tmp[2]; bf[1][1] = tmp[3];
            ldm_x4(uBhi + boff + kadd + (uint32_t)(16 * RS) * 2, tmp);
            bf[2][0] = tmp[0]; bf[2][1] = tmp[1]; bf[3][0] = tmp[2]; bf[3][1] = tmp[3];
#pragma unroll
            for (int mi = 0; mi < 4; mi++)
#pragma unroll
                for (int ni = 0; ni < 4; ni++)
                    mma16816(acc[mi][ni], ah[mi], bf[ni]);
            // A lo x B hi
            uint32_t al[4][4];
#pragma unroll
            for (int mi = 0; mi < 4; mi++)
                ldm_x4(uAlo + aoff + kadd + (uint32_t)(mi * 16 * RS) * 2, al[mi]);
#pragma unroll
            for (int mi = 0; mi < 4; mi++)
#pragma unroll
                for (int ni = 0; ni < 4; ni++)
                    mma16816(acc[mi][ni], al[mi], bf[ni]);
            // A hi x B lo
            ldm_x4(uBlo + boff + kadd, tmp);
            bf[0][0] = tmp[0]; bf[0][1] = tmp[1]; bf[1][0] = tmp[2]; bf[1][1] = tmp[3];
            ldm_x4(uBlo + boff + kadd + (uint32_t)(16 * RS) * 2, tmp);
            bf[2][0] = tmp[0]; bf[2][1] = tmp[1]; bf[3][0] = tmp[2]; bf[3][1] = tmp[3];
#pragma unroll
            for (int mi = 0; mi < 4; mi++)
#pragma unroll
                for (int ni = 0; ni < 4; ni++)
                    mma16816(acc[mi][ni], ah[mi], bf[ni]);
        }
        __syncthreads();
    }

    // ---- epilogue: bias, stores, per-channel BN partials ----
    float* red  = (float*)sAhi;       // 128 ch x 4 wn sums
    float* red2 = red + 512;

#pragma unroll
    for (int mi = 0; mi < 4; mi++) {
#pragma unroll
        for (int rh = 0; rh < 2; rh++) {
            int ch = m0 + wm * 64 + mi * 16 + (lane >> 2) + rh * 8;
            float bi = __ldg(&bias[ch]);
            float s = 0.0f, s2 = 0.0f;
#pragma unroll
            for (int ni = 0; ni < 4; ni++) {
#pragma unroll
                for (int jc = 0; jc < 2; jc++) {
                    float v = acc[mi][ni][rh * 2 + jc] + bi;
                    s += v; s2 += v * v;
                    int n = n0 + wn * 32 + ni * 8 + (lane & 3) * 2 + jc;
                    outp[((size_t)b * NN + n) * 256 + ch] = v;
                }
            }
            s  += __shfl_xor_sync(0xffffffffu, s, 1);
            s  += __shfl_xor_sync(0xffffffffu, s, 2);
            s2 += __shfl_xor_sync(0xffffffffu, s2, 1);
            s2 += __shfl_xor_sync(0xffffffffu, s2, 2);
            if ((lane & 3) == 0) {
                int chl = ch - m0;
                red[chl * 4 + wn]  = s;
                red2[chl * 4 + wn] = s2;
            }
        }
    }
    __syncthreads();
    if (tid < 128) {
        float s  = red[tid * 4]  + red[tid * 4 + 1]  + red[tid * 4 + 2]  + red[tid * 4 + 3];
        float s2 = red2[tid * 4] + red2[tid * 4 + 1] + red2[tid * 4 + 2] + red2[tid * 4 + 3];
        int slot = b * NT + blockIdx.x;
        g_psum[slot * 256 + m0 + tid] = s;
        g_psq[slot * 256 + m0 + tid]  = s2;
    }
}

// ---------------- BN fit: reduce 256 partials per channel ----------------
__global__ void __launch_bounds__(128) bnfit_kernel(const float* __restrict__ gma,
                                                    const float* __restrict__ bet) {
    int o = blockIdx.x, tid = threadIdx.x;
    float s = 0.0f, s2 = 0.0f;
    for (int i = tid; i < 256; i += 128) {
        s  += g_psum[i * 256 + o];
        s2 += g_psq[i * 256 + o];
    }
    __shared__ float sh[128], sh2[128];
    sh[tid] = s; sh2[tid] = s2;
    __syncthreads();
    for (int off = 64; off; off >>= 1) {
        if (tid < off) { sh[tid] += sh[tid + off]; sh2[tid] += sh2[tid + off]; }
        __syncthreads();
    }
    if (tid == 0) {
        const float M = (float)(BB * NN);
        float m = sh[0] / M;
        float var = sh2[0] / M - m * m;
        float sc = gma[o] * rsqrtf(var + 1e-5f);
        g_scale[o] = sc;
        g_shift[o] = bet[o] - m * sc;
    }
}

// ---------------- final: BN2 + ReLU + transpose [n][c] -> out [c][n] ----------------
__global__ void __launch_bounds__(256) out_kernel(float* __restrict__ out) {
    __shared__ float t[32][33];
    int b = blockIdx.z, c0 = blockIdx.y * 32, n0 = blockIdx.x * 32;
    int tx = threadIdx.x & 31, ty = threadIdx.x >> 5;
#pragma unroll
    for (int r = 0; r < 4; r++) {
        int i = ty + r * 8;
        t[i][tx] = g_O[((size_t)b * NN + n0 + i) * 256 + c0 + tx];
    }
    __syncthreads();
#pragma unroll
    for (int r = 0; r < 4; r++) {
        int i = ty + r * 8;
        float sc = g_scale[c0 + i], sf = g_shift[c0 + i];
        out[((size_t)b * 256 + c0 + i) * NN + n0 + tx] =
            fmaxf(fmaf(t[tx][i], sc, sf), 0.0f);
    }
}

// ---------------- launch ----------------
extern "C" void kernel_launch(void* const* d_in, const int* in_sizes, int n_in,
                              void* d_out, int out_size) {
    const float* pos1 = (const float*)d_in[0];
    const float* pos2 = (const float*)d_in[1];
    const float* f1   = (const float*)d_in[2];
    const float* f2   = (const float*)d_in[3];
    const float* W1   = (const float*)d_in[4];
    const float* b1   = (const float*)d_in[5];
    const float* g1   = (const float*)d_in[6];
    const float* be1  = (const float*)d_in[7];
    const float* W2   = (const float*)d_in[8];
    const float* b2   = (const float*)d_in[9];
    const float* g2   = (const float*)d_in[10];
    const float* be2  = (const float*)d_in[11];
    float* out = (float*)d_out;

    knn_kernel<<<dim3(NN / 8, BB), 256>>>(pos1, pos2);
    tr_f2_kernel<<<dim3(SS / 32, D2 / 32, BB), 256>>>(f2);
    wsplit_kernel<0><<<(CMID * CIN + 255) / 256, 256>>>(W1, CMID * CIN);
    wsplit_kernel<1><<<(COUT * CMID + 255) / 256, 256>>>(W2, COUT * CMID);
    tr_f1_kernel<<<dim3(NN / 32, D1 / 32, BB), 256>>>(f1);
    interp_kernel<<<dim3(NN / 32, BB), 256>>>();

    gemm_tc<CIN, 0><<<dim3(NT, 2, BB), 256>>>(b1);
    bnfit_kernel<<<256, 128>>>(g1, be1);
    prep2_kernel<<<(BB * NN * CMID / 4) / 256, 256>>>();

    gemm_tc<CMID, 1><<<dim3(NT, 2, BB), 256>>>(b2);
    bnfit_kernel<<<256, 128>>>(g2, be2);

    out_kernel<<<dim3(NN / 32, 256 / 32, BB), 256>>>(out);
}